// round 16
// baseline (speedup 1.0000x reference)
#include <cuda_runtime.h>
#include <cuda_fp16.h>
#include <cstdint>

// ---------------------------------------------------------------------------
// MaskMultiheadAttention  (B=4, N=2048, C=256, H=8, Dh=32)
// out = (query + proj_o(attn_masked @ V), softmax(QK^T*scale))
// d_out layout: [out_query (B*N*C floats)] [attn_vis (B*H*N*N floats)]
// Attention: QT=128 flash-style two-pass (rowsum, then recompute+emit),
// mma.sync tf32 both GEMMs, per-tile fp16 S buffer, K/V natural layout.
// ---------------------------------------------------------------------------

constexpr int B_ = 4, N_ = 2048, C_ = 256, H_ = 8, D_ = 32;
constexpr float SCALE_L2 = 0.17677669529663687f * 1.4426950408889634f;

__device__ float  g_q [B_ * N_ * C_];
__device__ float  g_k [B_ * N_ * C_];
__device__ float  g_v [B_ * N_ * C_];
__device__ float  g_x [B_ * N_ * C_];
__device__ __half g_mt[(size_t)B_ * N_ * N_];   // mask^T/colmax (fp16)
__device__ int    g_cmax[B_ * N_];

#define DEV_INLINE __device__ __forceinline__
typedef unsigned long long ull;

DEV_INLINE ull pk2(float lo, float hi) {
    ull r; asm("mov.b64 %0, {%1, %2};" : "=l"(r) : "f"(lo), "f"(hi)); return r;
}
DEV_INLINE float2 upk2(ull v) {
    float2 f; asm("mov.b64 {%0, %1}, %2;" : "=f"(f.x), "=f"(f.y) : "l"(v)); return f;
}
DEV_INLINE ull ffma2(ull a, ull b, ull c) {
    ull d; asm("fma.rn.f32x2 %0, %1, %2, %3;" : "=l"(d) : "l"(a), "l"(b), "l"(c)); return d;
}
DEV_INLINE float ex2f(float x) {
    float y; asm("ex2.approx.ftz.f32 %0, %1;" : "=f"(y) : "f"(x)); return y;
}
DEV_INLINE uint32_t fb(float x) { return __float_as_uint(x); }

// m16n8k8 tf32 MMA, row.col. Per-lane (g=lane>>2, tq=lane&3):
//  A: a0=(g,tq) a1=(g+8,tq) a2=(g,tq+4) a3=(g+8,tq+4)
//  B: b0=(k=tq,n=g) b1=(k=tq+4,n=g)
//  D: d0=(g,2tq) d1=(g,2tq+1) d2=(g+8,2tq) d3=(g+8,2tq+1)
DEV_INLINE void mma8(float4& d, uint32_t a0, uint32_t a1, uint32_t a2, uint32_t a3,
                     uint32_t b0, uint32_t b1) {
    asm volatile("mma.sync.aligned.m16n8k8.row.col.f32.tf32.tf32.f32 "
                 "{%0,%1,%2,%3}, {%4,%5,%6,%7}, {%8,%9}, {%0,%1,%2,%3};"
                 : "+f"(d.x), "+f"(d.y), "+f"(d.z), "+f"(d.w)
                 : "r"(a0), "r"(a1), "r"(a2), "r"(a3), "r"(b0), "r"(b1));
}

// ---------------------------------------------------------------------------
// QKV GEMM (NT, fused 3 outputs) — FFMA2 (proven)
// ---------------------------------------------------------------------------
__global__ void __launch_bounds__(256) gemm_qkv(
    const float* __restrict__ A,
    const float* __restrict__ W0, const float* __restrict__ b0, float* __restrict__ o0,
    const float* __restrict__ W1, const float* __restrict__ b1, float* __restrict__ o1,
    const float* __restrict__ W2, const float* __restrict__ b2, float* __restrict__ o2) {
    __shared__ float As[2][16][64];
    __shared__ float Bs[2][3][16][64];
    const int t  = threadIdx.x;
    const int m0 = blockIdx.y * 64;
    const int n0 = blockIdx.x * 64;
    const int ty = t >> 4, tx = t & 15;
    const int lr = t >> 2;
    const int lk = (t & 3) * 4;

    const float4* Ap  = (const float4*)&A [(size_t)(m0 + lr) * C_ + lk];
    const float4* W0p = (const float4*)&W0[(size_t)(n0 + lr) * C_ + lk];
    const float4* W1p = (const float4*)&W1[(size_t)(n0 + lr) * C_ + lk];
    const float4* W2p = (const float4*)&W2[(size_t)(n0 + lr) * C_ + lk];

    float4 sa = Ap[0], s0 = W0p[0], s1 = W1p[0], s2 = W2p[0];
    {
        As[0][lk+0][lr]=sa.x; As[0][lk+1][lr]=sa.y; As[0][lk+2][lr]=sa.z; As[0][lk+3][lr]=sa.w;
        Bs[0][0][lk+0][lr]=s0.x; Bs[0][0][lk+1][lr]=s0.y; Bs[0][0][lk+2][lr]=s0.z; Bs[0][0][lk+3][lr]=s0.w;
        Bs[0][1][lk+0][lr]=s1.x; Bs[0][1][lk+1][lr]=s1.y; Bs[0][1][lk+2][lr]=s1.z; Bs[0][1][lk+3][lr]=s1.w;
        Bs[0][2][lk+0][lr]=s2.x; Bs[0][2][lk+1][lr]=s2.y; Bs[0][2][lk+2][lr]=s2.z; Bs[0][2][lk+3][lr]=s2.w;
    }
    __syncthreads();

    ull acc[3][4][2];
#pragma unroll
    for (int w = 0; w < 3; w++)
#pragma unroll
        for (int i = 0; i < 4; i++) { acc[w][i][0] = 0ull; acc[w][i][1] = 0ull; }

    for (int kt = 0; kt < 16; kt++) {
        const int cur = kt & 1;
        if (kt < 15) {
            sa = Ap[4*(kt+1)]; s0 = W0p[4*(kt+1)]; s1 = W1p[4*(kt+1)]; s2 = W2p[4*(kt+1)];
        }
#pragma unroll
        for (int kk = 0; kk < 16; kk++) {
            ull bv[3][2];
#pragma unroll
            for (int w = 0; w < 3; w++) {
                bv[w][0] = *(const ull*)&Bs[cur][w][kk][tx*4];
                bv[w][1] = *(const ull*)&Bs[cur][w][kk][tx*4+2];
            }
#pragma unroll
            for (int i = 0; i < 4; i++) {
                float a = As[cur][kk][ty*4+i];
                ull ad = pk2(a, a);
#pragma unroll
                for (int w = 0; w < 3; w++) {
                    acc[w][i][0] = ffma2(ad, bv[w][0], acc[w][i][0]);
                    acc[w][i][1] = ffma2(ad, bv[w][1], acc[w][i][1]);
                }
            }
        }
        if (kt < 15) {
            const int nb = cur ^ 1;
            As[nb][lk+0][lr]=sa.x; As[nb][lk+1][lr]=sa.y; As[nb][lk+2][lr]=sa.z; As[nb][lk+3][lr]=sa.w;
            Bs[nb][0][lk+0][lr]=s0.x; Bs[nb][0][lk+1][lr]=s0.y; Bs[nb][0][lk+2][lr]=s0.z; Bs[nb][0][lk+3][lr]=s0.w;
            Bs[nb][1][lk+0][lr]=s1.x; Bs[nb][1][lk+1][lr]=s1.y; Bs[nb][1][lk+2][lr]=s1.z; Bs[nb][1][lk+3][lr]=s1.w;
            Bs[nb][2][lk+0][lr]=s2.x; Bs[nb][2][lk+1][lr]=s2.y; Bs[nb][2][lk+2][lr]=s2.z; Bs[nb][2][lk+3][lr]=s2.w;
        }
        __syncthreads();
    }

    const float* bias[3] = {b0, b1, b2};
    float*       outp[3] = {o0, o1, o2};
#pragma unroll
    for (int w = 0; w < 3; w++)
#pragma unroll
        for (int i = 0; i < 4; i++) {
            int m = m0 + ty*4 + i;
#pragma unroll
            for (int p = 0; p < 2; p++) {
                int n = n0 + tx*4 + p*2;
                float2 v = upk2(acc[w][i][p]);
                v.x += bias[w][n]; v.y += bias[w][n+1];
                *(float2*)&outp[w][(size_t)m * C_ + n] = v;
            }
        }
}

// ---------------------------------------------------------------------------
// Output GEMM with bias + residual — FFMA2 (proven)
// ---------------------------------------------------------------------------
__global__ void __launch_bounds__(256) gemm_o(const float* __restrict__ A,
                                              const float* __restrict__ W,
                                              const float* __restrict__ bias,
                                              const float* __restrict__ res,
                                              float* __restrict__ out) {
    __shared__ float As[2][16][64];
    __shared__ float Bs[2][16][64];
    const int t  = threadIdx.x;
    const int m0 = blockIdx.y * 64;
    const int n0 = blockIdx.x * 64;
    const int ty = t >> 4, tx = t & 15;
    const int lr = t >> 2;
    const int lk = (t & 3) * 4;

    const float4* Ap = (const float4*)&A[(size_t)(m0 + lr) * C_ + lk];
    const float4* Wp = (const float4*)&W[(size_t)(n0 + lr) * C_ + lk];

    float4 sa = Ap[0], sw = Wp[0];
    As[0][lk+0][lr]=sa.x; As[0][lk+1][lr]=sa.y; As[0][lk+2][lr]=sa.z; As[0][lk+3][lr]=sa.w;
    Bs[0][lk+0][lr]=sw.x; Bs[0][lk+1][lr]=sw.y; Bs[0][lk+2][lr]=sw.z; Bs[0][lk+3][lr]=sw.w;
    __syncthreads();

    ull acc[4][2];
#pragma unroll
    for (int i = 0; i < 4; i++) { acc[i][0] = 0ull; acc[i][1] = 0ull; }

    for (int kt = 0; kt < 16; kt++) {
        const int cur = kt & 1;
        if (kt < 15) { sa = Ap[4*(kt+1)]; sw = Wp[4*(kt+1)]; }
#pragma unroll
        for (int kk = 0; kk < 16; kk++) {
            ull bv0 = *(const ull*)&Bs[cur][kk][tx*4];
            ull bv1 = *(const ull*)&Bs[cur][kk][tx*4+2];
#pragma unroll
            for (int i = 0; i < 4; i++) {
                float a = As[cur][kk][ty*4+i];
                ull ad = pk2(a, a);
                acc[i][0] = ffma2(ad, bv0, acc[i][0]);
                acc[i][1] = ffma2(ad, bv1, acc[i][1]);
            }
        }
        if (kt < 15) {
            const int nb = cur ^ 1;
            As[nb][lk+0][lr]=sa.x; As[nb][lk+1][lr]=sa.y; As[nb][lk+2][lr]=sa.z; As[nb][lk+3][lr]=sa.w;
            Bs[nb][lk+0][lr]=sw.x; Bs[nb][lk+1][lr]=sw.y; Bs[nb][lk+2][lr]=sw.z; Bs[nb][lk+3][lr]=sw.w;
        }
        __syncthreads();
    }
#pragma unroll
    for (int i = 0; i < 4; i++) {
        int m = m0 + ty*4 + i;
#pragma unroll
        for (int p = 0; p < 2; p++) {
            int n = n0 + tx*4 + p*2;
            float2 v = upk2(acc[i][p]);
            v.x += bias[n]   + res[(size_t)m * C_ + n];
            v.y += bias[n+1] + res[(size_t)m * C_ + n + 1];
            *(float2*)&out[(size_t)m * C_ + n] = v;
        }
    }
}

// ---------------------------------------------------------------------------
// mask: column max, then normalized transpose (fp16): g_mt[b][q][k]
// ---------------------------------------------------------------------------
__global__ void __launch_bounds__(256) cmax_init() {
    int i = blockIdx.x * 256 + threadIdx.x;
    if (i < B_ * N_) g_cmax[i] = 0;
}
__global__ void __launch_bounds__(256) cmax_k(const float* __restrict__ mask) {
    int q = blockIdx.x * 256 + threadIdx.x;
    int b = blockIdx.z;
    const float* p = mask + (size_t)b * N_ * N_ + (size_t)(blockIdx.y * 256) * N_ + q;
    float m = 0.f;
#pragma unroll 8
    for (int k = 0; k < 256; k++) m = fmaxf(m, p[(size_t)k * N_]);
    atomicMax(&g_cmax[b * N_ + q], __float_as_int(m));
}
__global__ void __launch_bounds__(256) mt_k(const float* __restrict__ mask) {
    __shared__ float tl[64][65];
    const int t  = threadIdx.x;
    const int k0 = blockIdx.x * 64, qq0 = blockIdx.y * 64, b = blockIdx.z;
#pragma unroll
    for (int i = 0; i < 16; i++) {
        int idx = t + 256 * i;
        int r = idx >> 6, c = idx & 63;
        tl[r][c] = mask[((size_t)(b * N_ + k0 + r)) * N_ + qq0 + c];
    }
    __syncthreads();
#pragma unroll
    for (int i = 0; i < 16; i++) {
        int idx = t + 256 * i;
        int r = idx >> 6, c = idx & 63;
        float ic = 1.0f / __int_as_float(g_cmax[b * N_ + qq0 + r]);
        g_mt[((size_t)(b * N_ + qq0 + r)) * N_ + k0 + c] = __float2half(tl[c][r] * ic);
    }
}

// ---------------------------------------------------------------------------
// flash-style attention: one CTA = (b, h, 128 q rows). 512 threads (16 warps).
// pass 1: rowsums (recompute); pass 2: S recompute -> vis + P -> PV.
// warp: mq = wid&3 (rows mq*32, 2 m-tiles), nh = wid>>2 (keys nh*32, 4 n-tiles)
// ---------------------------------------------------------------------------
constexpr int QT2   = 128;               // q rows per CTA
constexpr int KTW2  = 128;               // keys per tile
constexpr int NKT2  = N_ / KTW2;         // 16
constexpr int SBH   = 136;               // S-tile stride (halves)
constexpr int SBU2  = SBH / 4;           // 34 (uint2 units)
constexpr int KVS2  = 36;                // K/V smem row stride (floats)
constexpr int QFS2  = 36;                // q smem row stride
constexpr int XS2   = 34;                // X staging row stride (floats)
constexpr int OFF_K2 = QT2 * SBH / 2;    // sbuf floats = 8704
constexpr int OFF_V2 = OFF_K2 + KTW2 * KVS2;   // 13312
constexpr int OFF_Q2 = OFF_V2 + KTW2 * KVS2;   // 17920
constexpr int OFF_I2 = OFF_Q2 + QT2 * QFS2;    // 22528
constexpr int OFF_W2 = OFF_I2 + QT2;           // 22656 (wpart 16*32)
constexpr int SMF2   = OFF_W2 + 512;           // 23168
constexpr int SMB2   = SMF2 * 4;               // 92672 B

__global__ void __launch_bounds__(512) attn_k(float* __restrict__ attn_out) {
    extern __shared__ float sm[];
    __half* sbuf = (__half*)sm;           // per-tile S (fp16), 128 x 136
    uint2*  sb2  = (uint2*)sm;
    float*  sX   = sm;                    // X staging (reuse of sbuf region)
    float*  kvf  = sm + OFF_K2;           // K tile  128 x 36
    float*  vvf  = sm + OFF_V2;           // V tile  128 x 36
    float*  qf   = sm + OFF_Q2;           // Q       128 x 36
    float*  invs = sm + OFF_I2;           // [128]
    float*  wpart= sm + OFF_W2;           // [16 warps][32 rows]

    const int t    = threadIdx.x;
    const int wid  = t >> 5, lane = t & 31;
    const int g    = lane >> 2, tq = lane & 3;
    const int mq   = wid & 3;             // row block (mq*32)
    const int nh   = wid >> 2;            // key quarter (nh*32)
    const int q0   = blockIdx.x * QT2;
    const int h    = blockIdx.y;
    const int b    = blockIdx.z;

    const float* qsrc = g_q + ((size_t)b * N_ + q0) * C_ + h * D_;
    const float* ksrc = g_k + (size_t)b * N_ * C_ + h * D_;
    const float* vsrc = g_v + (size_t)b * N_ * C_ + h * D_;

    // ---- Q stage: 128 rows x 32, stride 36 ----
#pragma unroll
    for (int i = 0; i < 8; i++) {
        int idx = t + 512 * i;
        int qi = idx >> 5, d = idx & 31;
        qf[qi * QFS2 + d] = qsrc[(size_t)qi * C_ + d] * SCALE_L2;
    }

    float4 st[4];
    // prologue: K tile 0 (128 rows x 8 float4 = 2/thread)
#pragma unroll
    for (int i = 0; i < 2; i++) {
        int idx = t + 512 * i, kk = idx >> 3, j = idx & 7;
        st[i] = *(const float4*)&ksrc[(size_t)kk * C_ + j * 4];
    }
    __syncthreads();  // qf visible
#pragma unroll
    for (int i = 0; i < 2; i++) {
        int idx = t + 512 * i, kk = idx >> 3, j = idx & 7;
        *(float4*)&kvf[kk * KVS2 + j * 4] = st[i];
    }
    __syncthreads();

    // ---- Q A-fragments (loop-invariant): 2 m-tiles x 4 kc x 4 ----
    uint32_t qa[2][4][4];
#pragma unroll
    for (int mt = 0; mt < 2; mt++)
#pragma unroll
        for (int kc = 0; kc < 4; kc++) {
            int r0 = mq * 32 + mt * 16 + g, r1 = r0 + 8;
            qa[mt][kc][0] = fb(qf[r0 * QFS2 + 8*kc + tq]);
            qa[mt][kc][1] = fb(qf[r1 * QFS2 + 8*kc + tq]);
            qa[mt][kc][2] = fb(qf[r0 * QFS2 + 8*kc + tq + 4]);
            qa[mt][kc][3] = fb(qf[r1 * QFS2 + 8*kc + tq + 4]);
        }

    // ================= pass 1: rowsums =================
    float rs[2][2] = {{0.f, 0.f}, {0.f, 0.f}};
    for (int kt = 0; kt < NKT2; kt++) {
        if (kt < NKT2 - 1) {
            const int k0n = (kt + 1) * KTW2;
#pragma unroll
            for (int i = 0; i < 2; i++) {
                int idx = t + 512 * i, kk = idx >> 3, j = idx & 7;
                st[i] = *(const float4*)&ksrc[(size_t)(k0n + kk) * C_ + j * 4];
            }
        }
        float4 acc[2][4];
#pragma unroll
        for (int mt = 0; mt < 2; mt++)
#pragma unroll
            for (int nt = 0; nt < 4; nt++) acc[mt][nt] = make_float4(0.f, 0.f, 0.f, 0.f);
#pragma unroll
        for (int kc = 0; kc < 4; kc++) {
#pragma unroll
            for (int nt = 0; nt < 4; nt++) {
                const int tok = nh * 32 + 8*nt + g;
                uint32_t b0 = fb(kvf[tok * KVS2 + 8*kc + tq]);
                uint32_t b1 = fb(kvf[tok * KVS2 + 8*kc + tq + 4]);
                mma8(acc[0][nt], qa[0][kc][0], qa[0][kc][1], qa[0][kc][2], qa[0][kc][3], b0, b1);
                mma8(acc[1][nt], qa[1][kc][0], qa[1][kc][1], qa[1][kc][2], qa[1][kc][3], b0, b1);
            }
        }
#pragma unroll
        for (int mt = 0; mt < 2; mt++)
#pragma unroll
            for (int nt = 0; nt < 4; nt++) {
                rs[mt][0] += ex2f(acc[mt][nt].x) + ex2f(acc[mt][nt].y);
                rs[mt][1] += ex2f(acc[mt][nt].z) + ex2f(acc[mt][nt].w);
            }
        __syncthreads();
        if (kt < NKT2 - 1) {
#pragma unroll
            for (int i = 0; i < 2; i++) {
                int idx = t + 512 * i, kk = idx >> 3, j = idx & 7;
                *(float4*)&kvf[kk * KVS2 + j * 4] = st[i];
            }
            __syncthreads();
        }
    }
    // quad reduce, cross-warp partials
#pragma unroll
    for (int mt = 0; mt < 2; mt++) {
        rs[mt][0] += __shfl_xor_sync(0xffffffffu, rs[mt][0], 1);
        rs[mt][0] += __shfl_xor_sync(0xffffffffu, rs[mt][0], 2);
        rs[mt][1] += __shfl_xor_sync(0xffffffffu, rs[mt][1], 1);
        rs[mt][1] += __shfl_xor_sync(0xffffffffu, rs[mt][1], 2);
    }
    if (tq == 0) {
#pragma unroll
        for (int mt = 0; mt < 2; mt++) {
            wpart[wid * 32 + mt*16 + g]     = rs[mt][0];
            wpart[wid * 32 + mt*16 + g + 8] = rs[mt][1];
        }
    }
    // prefetch K0 + V0 for pass 2
#pragma unroll
    for (int i = 0; i < 2; i++) {
        int idx = t + 512 * i, kk = idx >> 3, j = idx & 7;
        st[i]     = *(const float4*)&ksrc[(size_t)kk * C_ + j * 4];
        st[i + 2] = *(const float4*)&vsrc[(size_t)kk * C_ + j * 4];
    }
    __syncthreads();
    if (t < QT2) {
        float s = wpart[( 0 + (t >> 5)) * 32 + (t & 31)]
                + wpart[( 4 + (t >> 5)) * 32 + (t & 31)]
                + wpart[( 8 + (t >> 5)) * 32 + (t & 31)]
                + wpart[(12 + (t >> 5)) * 32 + (t & 31)];
        invs[t] = 1.0f / s;
    }
#pragma unroll
    for (int i = 0; i < 2; i++) {
        int idx = t + 512 * i, kk = idx >> 3, j = idx & 7;
        *(float4*)&kvf[kk * KVS2 + j * 4] = st[i];
        *(float4*)&vvf[kk * KVS2 + j * 4] = st[i + 2];
    }
    __syncthreads();

    // per-row invs (constant through pass 2)
    float iv[2][2];
#pragma unroll
    for (int mt = 0; mt < 2; mt++) {
        iv[mt][0] = invs[mq * 32 + mt*16 + g];
        iv[mt][1] = invs[mq * 32 + mt*16 + g + 8];
    }

    float* visbase = attn_out + (((size_t)b * H_ + h) * N_ + q0) * N_;
    const __half* mtbase = g_mt + (size_t)b * N_ * N_ + (size_t)q0 * N_;

    // ================= pass 2: emit vis + PV =================
    float4 acc2[2][4];
#pragma unroll
    for (int mt = 0; mt < 2; mt++)
#pragma unroll
        for (int nt = 0; nt < 4; nt++) acc2[mt][nt] = make_float4(0.f, 0.f, 0.f, 0.f);

    for (int kt = 0; kt < NKT2; kt++) {
        if (kt < NKT2 - 1) {
            const int k0n = (kt + 1) * KTW2;
#pragma unroll
            for (int i = 0; i < 2; i++) {
                int idx = t + 512 * i, kk = idx >> 3, j = idx & 7;
                st[i]     = *(const float4*)&ksrc[(size_t)(k0n + kk) * C_ + j * 4];
                st[i + 2] = *(const float4*)&vsrc[(size_t)(k0n + kk) * C_ + j * 4];
            }
        }
        // S tile
        float4 acc[2][4];
#pragma unroll
        for (int mt = 0; mt < 2; mt++)
#pragma unroll
            for (int nt = 0; nt < 4; nt++) acc[mt][nt] = make_float4(0.f, 0.f, 0.f, 0.f);
#pragma unroll
        for (int kc = 0; kc < 4; kc++) {
#pragma unroll
            for (int nt = 0; nt < 4; nt++) {
                const int tok = nh * 32 + 8*nt + g;
                uint32_t b0 = fb(kvf[tok * KVS2 + 8*kc + tq]);
                uint32_t b1 = fb(kvf[tok * KVS2 + 8*kc + tq + 4]);
                mma8(acc[0][nt], qa[0][kc][0], qa[0][kc][1], qa[0][kc][2], qa[0][kc][3], b0, b1);
                mma8(acc[1][nt], qa[1][kc][0], qa[1][kc][1], qa[1][kc][2], qa[1][kc][3], b0, b1);
            }
        }
        // e * invs -> sbuf (fp16)
#pragma unroll
        for (int mt = 0; mt < 2; mt++)
#pragma unroll
            for (int nt = 0; nt < 4; nt++) {
                int r0 = mq*32 + mt*16 + g, r1 = r0 + 8;
                int col = nh*32 + 8*nt + 2*tq;
                float e0 = ex2f(acc[mt][nt].x) * iv[mt][0];
                float e1 = ex2f(acc[mt][nt].y) * iv[mt][0];
                float e2 = ex2f(acc[mt][nt].z) * iv[mt][1];
                float e3 = ex2f(acc[mt][nt].w) * iv[mt][1];
                *(__half2*)&sbuf[(size_t)r0 * SBH + col] = __floats2half2_rn(e0, e1);
                *(__half2*)&sbuf[(size_t)r1 * SBH + col] = __floats2half2_rn(e2, e3);
            }
        __syncthreads();
        // vis write + mask fold (tile-wide, coalesced)
        {
            const int kb = kt * KTW2;
#pragma unroll
            for (int i = 0; i < 8; i++) {
                int idx = t + 512 * i;
                int row = idx >> 5, c = idx & 31;
                uint2 pv = sb2[row * SBU2 + c];
                float2 f01 = __half22float2(*(__half2*)&pv.x);
                float2 f23 = __half22float2(*(__half2*)&pv.y);
                float4 v = make_float4(f01.x, f01.y, f23.x, f23.y);
                __stcs((float4*)&visbase[(size_t)row * N_ + kb + 4*c], v);
                uint2 mv = *(const uint2*)&mtbase[(size_t)row * N_ + kb + 4*c];
                float2 m01 = __half22float2(*(__half2*)&mv.x);
                float2 m23 = __half22float2(*(__half2*)&mv.y);
                uint2 outp;
                *(__half2*)&outp.x = __floats2half2_rn(v.x * m01.x, v.y * m01.y);
                *(__half2*)&outp.y = __floats2half2_rn(v.z * m23.x, v.w * m23.y);
                sb2[row * SBU2 + c] = outp;
            }
        }
        __syncthreads();
        // PV: split-K (warp handles its nh quarter of this tile's keys)
#pragma unroll
        for (int kc = 0; kc < 4; kc++) {
            const int kb = nh * 32 + 8 * kc;   // tile-local key base
            uint32_t pa[2][4];
#pragma unroll
            for (int mt = 0; mt < 2; mt++) {
                int r0 = mq*32 + mt*16 + g, r1 = r0 + 8;
                pa[mt][0] = fb(__half2float(sbuf[(size_t)r0 * SBH + kb + tq]));
                pa[mt][1] = fb(__half2float(sbuf[(size_t)r1 * SBH + kb + tq]));
                pa[mt][2] = fb(__half2float(sbuf[(size_t)r0 * SBH + kb + tq + 4]));
                pa[mt][3] = fb(__half2float(sbuf[(size_t)r1 * SBH + kb + tq + 4]));
            }
#pragma unroll
            for (int nt = 0; nt < 4; nt++) {
                uint32_t b0 = fb(vvf[(kb + tq)     * KVS2 + 8*nt + g]);
                uint32_t b1 = fb(vvf[(kb + tq + 4) * KVS2 + 8*nt + g]);
                mma8(acc2[0][nt], pa[0][0], pa[0][1], pa[0][2], pa[0][3], b0, b1);
                mma8(acc2[1][nt], pa[1][0], pa[1][1], pa[1][2], pa[1][3], b0, b1);
            }
        }
        __syncthreads();
        if (kt < NKT2 - 1) {
#pragma unroll
            for (int i = 0; i < 2; i++) {
                int idx = t + 512 * i, kk = idx >> 3, j = idx & 7;
                *(float4*)&kvf[kk * KVS2 + j * 4] = st[i];
                *(float4*)&vvf[kk * KVS2 + j * 4] = st[i + 2];
            }
            __syncthreads();
        }
    }

    // ---- combine split-K partials across nh (4 warps per row block) ----
    if (nh >= 2) {
#pragma unroll
        for (int mt = 0; mt < 2; mt++)
#pragma unroll
            for (int nt = 0; nt < 4; nt++) {
                int r = mq*32 + mt*16 + g, d = 8*nt + 2*tq;
                float* dst = sX + (nh - 2) * (QT2 * XS2);
                *(float2*)&dst[ r      * XS2 + d] = make_float2(acc2[mt][nt].x, acc2[mt][nt].y);
                *(float2*)&dst[(r + 8) * XS2 + d] = make_float2(acc2[mt][nt].z, acc2[mt][nt].w);
            }
    }
    __syncthreads();
    if (nh < 2) {
        const float* src = sX + nh * (QT2 * XS2);
#pragma unroll
        for (int mt = 0; mt < 2; mt++)
#pragma unroll
            for (int nt = 0; nt < 4; nt++) {
                int r = mq*32 + mt*16 + g, d = 8*nt + 2*tq;
                float2 p0 = *(const float2*)&src[ r      * XS2 + d];
                float2 p1 = *(const float2*)&src[(r + 8) * XS2 + d];
                acc2[mt][nt].x += p0.x; acc2[mt][nt].y += p0.y;
                acc2[mt][nt].z += p1.x; acc2[mt][nt].w += p1.y;
            }
    }
    __syncthreads();
    if (nh == 1) {
#pragma unroll
        for (int mt = 0; mt < 2; mt++)
#pragma unroll
            for (int nt = 0; nt < 4; nt++) {
                int r = mq*32 + mt*16 + g, d = 8*nt + 2*tq;
                *(float2*)&sX[ r      * XS2 + d] = make_float2(acc2[mt][nt].x, acc2[mt][nt].y);
                *(float2*)&sX[(r + 8) * XS2 + d] = make_float2(acc2[mt][nt].z, acc2[mt][nt].w);
            }
    }
    __syncthreads();
    if (nh == 0) {
#pragma unroll
        for (int mt = 0; mt < 2; mt++)
#pragma unroll
            for (int nt = 0; nt < 4; nt++) {
                int r = mq*32 + mt*16 + g, d = 8*nt + 2*tq;
                float2 p0 = *(const float2*)&sX[ r      * XS2 + d];
                float2 p1 = *(const float2*)&sX[(r + 8) * XS2 + d];
                float2 o0 = make_float2(acc2[mt][nt].x + p0.x, acc2[mt][nt].y + p0.y);
                float2 o1 = make_float2(acc2[mt][nt].z + p1.x, acc2[mt][nt].w + p1.y);
                *(float2*)&g_x[((size_t)b * N_ + q0 + r)     * C_ + h * D_ + d] = o0;
                *(float2*)&g_x[((size_t)b * N_ + q0 + r + 8) * C_ + h * D_ + d] = o1;
            }
    }
}

// ---------------------------------------------------------------------------
extern "C" void kernel_launch(void* const* d_in, const int* in_sizes, int n_in,
                              void* d_out, int out_size) {
    (void)in_sizes; (void)n_in; (void)out_size;
    const float* query = (const float*)d_in[0];
    const float* mask  = (const float*)d_in[1];
    const float* Wq    = (const float*)d_in[2];
    const float* bq    = (const float*)d_in[3];
    const float* Wk    = (const float*)d_in[4];
    const float* bk    = (const float*)d_in[5];
    const float* Wv    = (const float*)d_in[6];
    const float* bv    = (const float*)d_in[7];
    const float* Wo    = (const float*)d_in[8];
    const float* bo    = (const float*)d_in[9];

    float* out      = (float*)d_out;
    float* attn_out = out + (size_t)B_ * N_ * C_;

    void* p;
    cudaGetSymbolAddress(&p, g_q);   float* gq = (float*)p;
    cudaGetSymbolAddress(&p, g_k);   float* gk = (float*)p;
    cudaGetSymbolAddress(&p, g_v);   float* gv = (float*)p;
    cudaGetSymbolAddress(&p, g_x);   float* gx = (float*)p;

    cudaFuncSetAttribute(attn_k, cudaFuncAttributeMaxDynamicSharedMemorySize, SMB2);

    dim3 gg(4, 128);
    gemm_qkv<<<gg, 256>>>(query, Wq, bq, gq, Wk, bk, gk, Wv, bv, gv);

    cmax_init<<<(B_ * N_ + 255) / 256, 256>>>();
    cmax_k<<<dim3(8, 8, 4), 256>>>(mask);
    mt_k<<<dim3(N_ / 64, N_ / 64, B_), 256>>>(mask);

    attn_k<<<dim3(N_ / QT2, H_, B_), 512, SMB2>>>(attn_out);

    gemm_o<<<gg, 256>>>(gx, Wo, bo, query, out);
}